// round 15
// baseline (speedup 1.0000x reference)
#include <cuda_runtime.h>

#define NB 16
#define NPTS 4096
#define NP 512
#define NS 32
#define MROWS (NB*NP*NS)   // 262144 rows
#define NQ (NB*NP)         // 8192 queries
#define CAP 1024
#define MB2 1024           // mlp grid blocks (MROWS/256)

typedef unsigned long long u64;
typedef unsigned int u32;

// ---------------- scratch ----------------
__device__ float g_newxyz[NQ*3];
__device__ u32 g_prog[NB*32];
__device__ float g_h1[64*MROWS];
__device__ float g_h2[64*MROWS];
__device__ float g_p1s[64*NQ];
__device__ float g_p1q[64*NQ];
__device__ float g_p2s[64*MB2];
__device__ float g_p2q[64*MB2];
__device__ float g_p3s[128*MB2];
__device__ float g_p3q[128*MB2];
__device__ float g_hmax[NQ*128];
__device__ float g_a1[64], g_c1[64];
__device__ float g_a2[64], g_c2[64];
__device__ float g_a3[128], g_c3[128];

// ---------------- helpers ----------------
__device__ __forceinline__ u64 pk(float lo, float hi) {
    u64 r; asm("mov.b64 %0,{%1,%2};" : "=l"(r) : "f"(lo), "f"(hi)); return r;
}
__device__ __forceinline__ void upk(u64 v, float& lo, float& hi) {
    asm("mov.b64 {%0,%1},%2;" : "=f"(lo), "=f"(hi) : "l"(v));
}
__device__ __forceinline__ u64 addx2(u64 a, u64 b) {
    u64 r; asm("add.rn.f32x2 %0,%1,%2;" : "=l"(r) : "l"(a), "l"(b)); return r;
}
__device__ __forceinline__ u64 mulx2(u64 a, u64 b) {
    u64 r; asm("mul.rn.f32x2 %0,%1,%2;" : "=l"(r) : "l"(a), "l"(b)); return r;
}
__device__ __forceinline__ void fma2(u64& acc, u64 w, u64 x) {
    asm("fma.rn.f32x2 %0, %1, %2, %0;" : "+l"(acc) : "l"(w), "l"(x));
}
__device__ __forceinline__ u32 rmaxu(u32 v) {
    u32 r; asm("redux.sync.max.u32 %0,%1,0xffffffff;" : "=r"(r) : "r"(v)); return r;
}
__device__ __forceinline__ u32 rminu(u32 v) {
    u32 r; asm("redux.sync.min.u32 %0,%1,0xffffffff;" : "=r"(r) : "r"(v)); return r;
}
__device__ __forceinline__ u32 f2ord(float f) {
    u32 b = __float_as_uint(f);
    return b ^ (0x80000000u | (u32)((int)b >> 31));
}
__device__ __forceinline__ u32 uno(u32 u) {
    return (u & 0x80000000u) ? (u ^ 0x80000000u) : ~u;
}

// =======================================================================
__global__ void init_kernel() {
    if (threadIdx.x < NB) g_prog[threadIdx.x * 32] = 0u;
}

// =======================================================================
// FPS body (R13 proven form: scalar dist mins, one barrier/iter,
// batched release publish, deferred out0 transpose)
// =======================================================================
__device__ void fps_body(int b, const float* __restrict__ xyz,
                         float* __restrict__ out0,
                         u64 (*swk)[16], float4 (*swc)[16]) {
    const int tid = threadIdx.x, wid = tid >> 5, lid = tid & 31;
    const float* base = xyz + (size_t)b * 3 * NPTS;

    u64 xp[4], yp[4], zp[4];
    float dist[8];
#pragma unroll
    for (int k = 0; k < 4; k++) {
        int n0 = tid + 512 * (2 * k), n1 = n0 + 512;
        xp[k] = pk(base[n0], base[n1]);
        yp[k] = pk(base[NPTS + n0], base[NPTS + n1]);
        zp[k] = pk(base[2 * NPTS + n0], base[2 * NPTS + n1]);
        dist[2 * k] = 1e10f; dist[2 * k + 1] = 1e10f;
    }
    float cx = base[0], cy = base[NPTS], cz = base[2 * NPTS];

    for (int it = 0; it < NP; it++) {
        if (tid == 0) {
            g_newxyz[((size_t)b * NP + it) * 3 + 0] = cx;
            g_newxyz[((size_t)b * NP + it) * 3 + 1] = cy;
            g_newxyz[((size_t)b * NP + it) * 3 + 2] = cz;
            if (((it + 1) & 3) == 0) {
                asm volatile("st.release.gpu.global.u32 [%0], %1;"
                             :: "l"(&g_prog[b * 32]), "r"((u32)(it + 1)) : "memory");
            }
        }
        u64 ncx = pk(-cx, -cx), ncy = pk(-cy, -cy), ncz = pk(-cz, -cz);
        float bd = -1.0f;
#pragma unroll
        for (int k = 0; k < 4; k++) {
            u64 dx = addx2(xp[k], ncx);
            u64 dy = addx2(yp[k], ncy);
            u64 dz = addx2(zp[k], ncz);
            u64 d2 = addx2(addx2(mulx2(dx, dx), mulx2(dy, dy)), mulx2(dz, dz));
            float lo, hi; upk(d2, lo, hi);
            dist[2 * k] = fminf(dist[2 * k], lo);
            dist[2 * k + 1] = fminf(dist[2 * k + 1], hi);
            bd = fmaxf(bd, fmaxf(dist[2 * k], dist[2 * k + 1]));
        }
        int bj = 0;
#pragma unroll
        for (int j = 7; j >= 0; j--) if (dist[j] == bd) bj = j;
        u32 bi = (u32)(tid + 512 * bj);
        u32 bb = __float_as_uint(bd);
        u32 m = rmaxu(bb);
        u32 cand = (bb == m) ? bi : 0xffffffffu;
        u32 pmin = rminu(cand);
        const int par = it & 1;
        if (bb == m && bi == pmin) {
            float wx = 0.f, wy = 0.f, wz = 0.f;
#pragma unroll
            for (int k = 0; k < 4; k++) {
                float xl, xh, yl, yh, zl, zh;
                upk(xp[k], xl, xh); upk(yp[k], yl, yh); upk(zp[k], zl, zh);
                if (bj == 2 * k)     { wx = xl; wy = yl; wz = zl; }
                if (bj == 2 * k + 1) { wx = xh; wy = yh; wz = zh; }
            }
            swk[par][wid] = ((u64)m << 32) | (u32)(NPTS - 1 - pmin);
            swc[par][wid] = make_float4(wx, wy, wz, 0.f);
        }
        __syncthreads();
        u64 kk = swk[par][lid & 15];
        u32 h = (u32)(kk >> 32), l = (u32)kk;
        u32 m2 = rmaxu(h);
        u32 c2 = (h == m2) ? l : 0u;
        u32 l2 = rmaxu(c2);
        u32 slotc = (h == m2 && l == l2) ? (u32)(lid & 15) : 0xffffffffu;
        u32 slot = rminu(slotc);
        float4 w = swc[par][slot];
        cx = w.x; cy = w.y; cz = w.z;
    }

    __syncthreads();
    {
        const float* nx = g_newxyz + (size_t)b * NP * 3;
        out0[((size_t)b * 3 + 0) * NP + tid] = nx[tid * 3 + 0];
        out0[((size_t)b * 3 + 1) * NP + tid] = nx[tid * 3 + 1];
        out0[((size_t)b * 3 + 2) * NP + tid] = nx[tid * 3 + 2];
    }
}

// =======================================================================
// Ball body (R13 structure, unchanged)
// =======================================================================
__device__ void ball_body(int b, int s, const float* __restrict__ xyz,
                          const float* __restrict__ points,
                          const float* __restrict__ W0,
                          const float* __restrict__ b0,
                          u64* cand, u32* scnt, u64* gm, u64* sgmin, u64* sel,
                          float (*frow)[32], float (*Wsh)[64], float* bsh) {
    const int tid = threadIdx.x, wid = tid >> 5, lid = tid & 31;
    const int q = b * NP + s;
    const float* base = xyz + (size_t)b * 3 * NPTS;
    const u32 uth = f2ord(0.04f);

    for (int i = tid; i < 9 * 64; i += 512) {
        int c = i / 64, o = i % 64;
        Wsh[c][o] = W0[o * 9 + c];
    }
    if (tid < 64) bsh[tid] = b0[tid];
    if (tid == 0) *scnt = 0u;

    u64 xp[4], yp[4], zp[4], pnp[4];
#pragma unroll
    for (int k = 0; k < 4; k++) {
        int n0 = tid + 512 * (2 * k), n1 = n0 + 512;
        xp[k] = pk(base[n0], base[n1]);
        yp[k] = pk(base[NPTS + n0], base[NPTS + n1]);
        zp[k] = pk(base[2 * NPTS + n0], base[2 * NPTS + n1]);
        pnp[k] = addx2(addx2(mulx2(xp[k], xp[k]), mulx2(yp[k], yp[k])),
                       mulx2(zp[k], zp[k]));
    }

    if (tid == 0) {
        u32 p;
        while (true) {
            asm volatile("ld.acquire.gpu.global.u32 %0,[%1];"
                         : "=r"(p) : "l"(&g_prog[b * 32]) : "memory");
            if (p > (u32)s) break;
            __nanosleep(64);
        }
    }
    __syncthreads();

    const float qx = g_newxyz[(size_t)q * 3 + 0];
    const float qy = g_newxyz[(size_t)q * 3 + 1];
    const float qz = g_newxyz[(size_t)q * 3 + 2];
    const float qn = __fadd_rn(__fadd_rn(__fmul_rn(qx, qx), __fmul_rn(qy, qy)),
                               __fmul_rn(qz, qz));
    u64 qxp = pk(qx, qx), qyp = pk(qy, qy), qzp = pk(qz, qz);
    u64 qnp = pk(qn, qn), n2p = pk(-2.0f, -2.0f);

    u64 key[8];
    u32 mask = 0, myCnt = 0;
    u64 loc = ~0ull;
#pragma unroll
    for (int k = 0; k < 4; k++) {
        u64 dt = addx2(addx2(mulx2(xp[k], qxp), mulx2(yp[k], qyp)),
                       mulx2(zp[k], qzp));
        u64 d = addx2(addx2(qnp, pnp[k]), mulx2(dt, n2p));
        float lo, hi; upk(d, lo, hi);
        int n0 = tid + 512 * (2 * k);
        u64 k0 = ((u64)f2ord(lo) << 32) | (u32)n0;
        u64 k1 = ((u64)f2ord(hi) << 32) | (u32)(n0 + 512);
        key[2 * k] = k0; key[2 * k + 1] = k1;
        u64 mn = (k0 < k1) ? k0 : k1;
        loc = (mn < loc) ? mn : loc;
        if ((u32)(k0 >> 32) <= uth) { mask |= 1u << (2 * k);     myCnt++; }
        if ((u32)(k1 >> 32) <= uth) { mask |= 1u << (2 * k + 1); myCnt++; }
    }

    u32 pre = myCnt;
#pragma unroll
    for (int off = 1; off < 32; off <<= 1) {
        u32 v = __shfl_up_sync(0xffffffffu, pre, off);
        if (lid >= off) pre += v;
    }
    u32 wtot = __shfl_sync(0xffffffffu, pre, 31);
    u32 wb = 0;
    if (lid == 31) wb = atomicAdd(scnt, wtot);
    wb = __shfl_sync(0xffffffffu, wb, 31);
    u32 pos = wb + pre - myCnt;
#pragma unroll
    for (int j = 0; j < 8; j++)
        if ((mask >> j) & 1) { if (pos < CAP) cand[pos] = key[j]; pos++; }

    {
        u32 hi = (u32)(loc >> 32);
        u32 m = rminu(hi);
        u32 c = (hi == m) ? (u32)loc : 0xffffffffu;
        u32 nm = rminu(c);
        if (lid == 0) gm[wid] = ((u64)m << 32) | nm;
    }
    __syncthreads();

    if (wid == 0) {
        u64 v = gm[lid & 15];
        u32 h2 = (u32)(v >> 32);
        u32 m2 = rminu(h2);
        u32 c2 = (h2 == m2) ? (u32)v : 0xffffffffu;
        u32 n2 = rminu(c2);
        if (lid == 0) *sgmin = ((u64)m2 << 32) | n2;

        u32 count = *scnt;
        if (count > CAP) count = CAP;
        int nslots = (int)((count + 31) >> 5);
        u64 loc0 = ~0ull;
        for (int j = 0; j < nslots; j++) {
            u32 p = (u32)lid + 32u * j;
            u64 kv = (p < count) ? cand[p] : ~0ull;
            loc0 = (kv < loc0) ? kv : loc0;
        }
        for (int k = 0; k < NS; k++) {
            u32 hi = (u32)(loc0 >> 32);
            u32 m = rminu(hi);
            u32 cd = (hi == m) ? (u32)loc0 : 0xffffffffu;
            u32 nm = rminu(cd);
            u64 wkey = ((u64)m << 32) | nm;
            if (lid == 0) sel[k] = wkey;
            if (loc0 == wkey && wkey != ~0ull) {
                loc0 = ~0ull;
                for (int j = 0; j < nslots; j++) {
                    u32 p = (u32)lid + 32u * j;
                    if (p < count) {
                        u64 kv = cand[p];
                        if (kv == wkey) { cand[p] = ~0ull; kv = ~0ull; }
                        loc0 = (kv < loc0) ? kv : loc0;
                    }
                }
            }
        }
    }
    __syncthreads();

    if (tid < NS) {
        u64 kk = sel[tid];
        u32 wd = (u32)(kk >> 32);
        u32 first_n = (u32)(*sgmin & 0xffffffffu);
        u32 idx = (wd > uth) ? first_n : (u32)(kk & 0xffffffffu);
        float x = base[idx], y = base[NPTS + idx], z = base[2 * NPTS + idx];
        frow[0][tid] = x - qx;
        frow[1][tid] = y - qy;
        frow[2][tid] = z - qz;
        const float* pb = points + (size_t)b * 6 * NPTS;
#pragma unroll
        for (int d = 0; d < 6; d++) frow[3 + d][tid] = pb[(size_t)d * NPTS + idx];
    }
    __syncthreads();

    {
        const int r = lid, og = wid;
        float acc[4];
#pragma unroll
        for (int i = 0; i < 4; i++) acc[i] = bsh[og * 4 + i];
#pragma unroll
        for (int c = 0; c < 9; c++) {
            float f = frow[c][r];
#pragma unroll
            for (int i = 0; i < 4; i++) acc[i] = fmaf(Wsh[c][og * 4 + i], f, acc[i]);
        }
        float* hb = g_h1 + (size_t)q * NS + r;
#pragma unroll
        for (int i = 0; i < 4; i++) hb[(size_t)(og * 4 + i) * MROWS] = acc[i];

        float sv[4], qv[4];
#pragma unroll
        for (int i = 0; i < 4; i++) {
            sv[i] = acc[i];
            qv[i] = acc[i] * acc[i];
#pragma unroll
            for (int off = 1; off < 32; off <<= 1) {
                sv[i] += __shfl_xor_sync(0xffffffffu, sv[i], off);
                qv[i] += __shfl_xor_sync(0xffffffffu, qv[i], off);
            }
        }
        if (lid == 0) {
#pragma unroll
            for (int i = 0; i < 4; i++) {
                g_p1s[(size_t)(og * 4 + i) * NQ + q] = sv[i];
                g_p1q[(size_t)(og * 4 + i) * NQ + q] = qv[i];
            }
        }
    }
}

__global__ void __launch_bounds__(512, 2) fused_fps_ball(const float* __restrict__ xyz,
                                                         const float* __restrict__ points,
                                                         const float* __restrict__ W0,
                                                         const float* __restrict__ b0,
                                                         float* __restrict__ out0) {
    __shared__ u64 swk[2][16];
    __shared__ float4 swc[2][16];
    __shared__ u64 cand[CAP];
    __shared__ u32 scnt;
    __shared__ u64 gm[16];
    __shared__ u64 sgmin;
    __shared__ u64 sel[NS];
    __shared__ float frow[9][32];
    __shared__ float Wsh[9][64];
    __shared__ float bsh[64];

    const int bid = blockIdx.x;
    if (bid < NB) {
        fps_body(bid, xyz, out0, swk, swc);
    } else {
        int b, s;
        if (bid >= 148 && bid < 148 + NB) {
            s = NP - 1; b = bid - 148;
        } else {
            int idx = (bid < 148) ? (bid - NB) : (bid - 2 * NB);
            b = idx & 15; s = idx >> 4;
        }
        ball_body(b, s, xyz, points, W0, b0,
                  cand, &scnt, gm, &sgmin, sel, frow, Wsh, bsh);
    }
}

// =======================================================================
// comb_part: BN coeffs from per-channel partial arrays (stride n).
// =======================================================================
__global__ void __launch_bounds__(256) comb_part(const float* __restrict__ ps,
                                                 const float* __restrict__ pq,
                                                 const float* __restrict__ g,
                                                 const float* __restrict__ be,
                                                 float* __restrict__ a,
                                                 float* __restrict__ c, int n) {
    const int ch = blockIdx.x, tid = threadIdx.x;
    const float* s0 = ps + (size_t)ch * n;
    const float* q0 = pq + (size_t)ch * n;
    float s = 0.f, s2 = 0.f;
    for (int i = tid; i < n; i += 256) { s += s0[i]; s2 += q0[i]; }
    __shared__ float sh[256], sh2[256];
    sh[tid] = s; sh2[tid] = s2;
    __syncthreads();
    for (int off = 128; off > 0; off >>= 1) {
        if (tid < off) { sh[tid] += sh[tid + off]; sh2[tid] += sh2[tid + off]; }
        __syncthreads();
    }
    if (tid == 0) {
        double mean = (double)sh[0] / (double)MROWS;
        double var = (double)sh2[0] / (double)MROWS - mean * mean;
        double af = (double)g[ch] / sqrt(var + 1e-5);
        a[ch] = (float)af;
        c[ch] = (float)((double)be[ch] - mean * af);
    }
}

// =======================================================================
// MLP layer 2 (64->64), 2-row tiling, 3 blocks/SM occupancy target.
// =======================================================================
__global__ void __launch_bounds__(256, 3) mlp2_kernel(const float* __restrict__ in,
                                                      const float* __restrict__ W,
                                                      const float* __restrict__ bias,
                                                      const float* __restrict__ aP,
                                                      const float* __restrict__ cP,
                                                      float* __restrict__ out) {
    __shared__ __align__(16) float Wsh[64][64];
    __shared__ float bsh[64], ash[64], csh[64];
    __shared__ u64 sS[8][16], sQ[8][16];
    const int tid = threadIdx.x, wid = tid >> 5, lid = tid & 31;
    const int rt = tid & 127, half = tid >> 7;
    const int o0 = half * 32;

    for (int i = tid; i < 64 * 64; i += 256) {
        int c = i >> 6, o = i & 63;
        Wsh[c][o] = W[(size_t)o * 64 + c];
    }
    if (tid < 64) { bsh[tid] = bias[tid]; ash[tid] = aP[tid]; csh[tid] = cP[tid]; }
    __syncthreads();

    const size_t r0 = (size_t)blockIdx.x * 256 + rt;
    const float* inr = in + r0;

    u64 acc[32];
#pragma unroll
    for (int k = 0; k < 16; k++) {
        u64 bb = pk(bsh[o0 + 2 * k], bsh[o0 + 2 * k + 1]);
        acc[k] = bb; acc[16 + k] = bb;
    }

#pragma unroll 8
    for (int c = 0; c < 64; c++) {
        float xa = inr[(size_t)c * MROWS];
        float xb = inr[(size_t)c * MROWS + 128];
        float av = ash[c], cv = csh[c];
        xa = fmaxf(fmaf(av, xa, cv), 0.0f);
        xb = fmaxf(fmaf(av, xb, cv), 0.0f);
        u64 x0 = pk(xa, xa), x1 = pk(xb, xb);
        const ulonglong2* w4 = reinterpret_cast<const ulonglong2*>(&Wsh[c][o0]);
#pragma unroll
        for (int k4 = 0; k4 < 8; k4++) {
            ulonglong2 w = w4[k4];
            fma2(acc[2 * k4 + 0], w.x, x0);
            fma2(acc[2 * k4 + 1], w.y, x0);
            fma2(acc[16 + 2 * k4 + 0], w.x, x1);
            fma2(acc[16 + 2 * k4 + 1], w.y, x1);
        }
    }

    float* outr = out + r0;
#pragma unroll
    for (int k = 0; k < 16; k++) {
        float lo, hi;
        upk(acc[k], lo, hi);
        outr[(size_t)(o0 + 2 * k) * MROWS] = lo;
        outr[(size_t)(o0 + 2 * k + 1) * MROWS] = hi;
        upk(acc[16 + k], lo, hi);
        outr[(size_t)(o0 + 2 * k) * MROWS + 128] = lo;
        outr[(size_t)(o0 + 2 * k + 1) * MROWS + 128] = hi;
    }

#pragma unroll
    for (int k = 0; k < 16; k++) {
        u64 sv = addx2(acc[k], acc[16 + k]);
        u64 qv = addx2(mulx2(acc[k], acc[k]), mulx2(acc[16 + k], acc[16 + k]));
#pragma unroll
        for (int off = 1; off < 32; off <<= 1) {
            sv = addx2(sv, __shfl_xor_sync(0xffffffffu, sv, off));
            qv = addx2(qv, __shfl_xor_sync(0xffffffffu, qv, off));
        }
        if (lid == 0) { sS[wid][k] = sv; sQ[wid][k] = qv; }
    }
    __syncthreads();
    if (tid < 128) {
        int ch = tid & 63;
        bool isq = tid >= 64;
        int h = ch >> 5, k = (ch & 31) >> 1, lohi = ch & 1;
        const u64 (*src)[16] = isq ? sQ : sS;
        u64 t = src[4 * h][k];
#pragma unroll
        for (int w = 1; w < 4; w++) t = addx2(t, src[4 * h + w][k]);
        float lo, hi; upk(t, lo, hi);
        (isq ? g_p2q : g_p2s)[(size_t)ch * MB2 + blockIdx.x] = lohi ? hi : lo;
    }
}

// =======================================================================
// MLP layer 3 (64->128 via y-halves), 2-row tiling, NO h3 store,
// 3 blocks/SM target. Epilogue: stat partials + per-query channel max.
// =======================================================================
__global__ void __launch_bounds__(256, 3) mlp3_kernel(const float* __restrict__ in,
                                                      const float* __restrict__ W,
                                                      const float* __restrict__ bias,
                                                      const float* __restrict__ aP,
                                                      const float* __restrict__ cP) {
    __shared__ __align__(16) float Wsh[64][64];
    __shared__ float bsh[64], ash[64], csh[64];
    __shared__ u64 sS[8][16], sQ[8][16];
    const int tid = threadIdx.x, wid = tid >> 5, lid = tid & 31;
    const int rt = tid & 127, half = tid >> 7;
    const int o0 = half * 32;
    const int ocb = blockIdx.y * 64;

    for (int i = tid; i < 64 * 64; i += 256) {
        int c = i >> 6, o = i & 63;
        Wsh[c][o] = W[(size_t)(ocb + o) * 64 + c];
    }
    if (tid < 64) { bsh[tid] = bias[ocb + tid]; ash[tid] = aP[tid]; csh[tid] = cP[tid]; }
    __syncthreads();

    const size_t r0 = (size_t)blockIdx.x * 256 + rt;
    const float* inr = in + r0;

    u64 acc[32];
#pragma unroll
    for (int k = 0; k < 16; k++) {
        u64 bb = pk(bsh[o0 + 2 * k], bsh[o0 + 2 * k + 1]);
        acc[k] = bb; acc[16 + k] = bb;
    }

#pragma unroll 8
    for (int c = 0; c < 64; c++) {
        float xa = inr[(size_t)c * MROWS];
        float xb = inr[(size_t)c * MROWS + 128];
        float av = ash[c], cv = csh[c];
        xa = fmaxf(fmaf(av, xa, cv), 0.0f);
        xb = fmaxf(fmaf(av, xb, cv), 0.0f);
        u64 x0 = pk(xa, xa), x1 = pk(xb, xb);
        const ulonglong2* w4 = reinterpret_cast<const ulonglong2*>(&Wsh[c][o0]);
#pragma unroll
        for (int k4 = 0; k4 < 8; k4++) {
            ulonglong2 w = w4[k4];
            fma2(acc[2 * k4 + 0], w.x, x0);
            fma2(acc[2 * k4 + 1], w.y, x0);
            fma2(acc[16 + 2 * k4 + 0], w.x, x1);
            fma2(acc[16 + 2 * k4 + 1], w.y, x1);
        }
    }

#pragma unroll
    for (int k = 0; k < 16; k++) {
        u64 sv = addx2(acc[k], acc[16 + k]);
        u64 qv = addx2(mulx2(acc[k], acc[k]), mulx2(acc[16 + k], acc[16 + k]));
#pragma unroll
        for (int off = 1; off < 32; off <<= 1) {
            sv = addx2(sv, __shfl_xor_sync(0xffffffffu, sv, off));
            qv = addx2(qv, __shfl_xor_sync(0xffffffffu, qv, off));
        }
        if (lid == 0) { sS[wid][k] = sv; sQ[wid][k] = qv; }
    }

    {
        const int qa = blockIdx.x * 8 + (wid & 3);
        const int qb = qa + 4;
        const int cb2 = (ocb + o0) >> 1;
        float2* hmax2 = reinterpret_cast<float2*>(g_hmax);
#pragma unroll
        for (int k = 0; k < 16; k++) {
            float lo, hi;
            upk(acc[k], lo, hi);
            u32 a0 = rmaxu(f2ord(lo)), b0v = rmaxu(f2ord(hi));
            upk(acc[16 + k], lo, hi);
            u32 a1 = rmaxu(f2ord(lo)), b1v = rmaxu(f2ord(hi));
            if (lid == 0) {
                hmax2[(size_t)qa * 64 + cb2 + k] =
                    make_float2(__uint_as_float(uno(a0)), __uint_as_float(uno(b0v)));
                hmax2[(size_t)qb * 64 + cb2 + k] =
                    make_float2(__uint_as_float(uno(a1)), __uint_as_float(uno(b1v)));
            }
        }
    }
    __syncthreads();
    if (tid < 128) {
        int ch = tid & 63;
        bool isq = tid >= 64;
        int h = ch >> 5, k = (ch & 31) >> 1, lohi = ch & 1;
        const u64 (*src)[16] = isq ? sQ : sS;
        u64 t = src[4 * h][k];
#pragma unroll
        for (int w = 1; w < 4; w++) t = addx2(t, src[4 * h + w][k]);
        float lo, hi; upk(t, lo, hi);
        (isq ? g_p3q : g_p3s)[(size_t)(ocb + ch) * MB2 + blockIdx.x] = lohi ? hi : lo;
    }
}

// =======================================================================
// final: out = relu(a3*hmax + c3)  (a3>0 so max commutes exactly)
// =======================================================================
__global__ void __launch_bounds__(1024) final_kernel(float* __restrict__ out) {
    const int t = blockIdx.x * 1024 + threadIdx.x;
    const int q = t >> 7, o = t & 127;
    float v = g_hmax[t];
    float y = fmaxf(fmaf(g_a3[o], v, g_c3[o]), 0.0f);
    const int b = q >> 9, s = q & 511;
    out[(size_t)NB * 3 * NP + (((size_t)b * 128 + o) << 9) + s] = y;
}

// ---------------- launch ----------------
extern "C" void kernel_launch(void* const* d_in, const int* in_sizes, int n_in,
                              void* d_out, int out_size) {
    const float* xyz = (const float*)d_in[0];
    const float* pts = (const float*)d_in[1];
    const float* W0 = (const float*)d_in[2];
    const float* b0 = (const float*)d_in[3];
    const float* g0 = (const float*)d_in[4];
    const float* be0 = (const float*)d_in[5];
    const float* W1 = (const float*)d_in[6];
    const float* b1 = (const float*)d_in[7];
    const float* g1 = (const float*)d_in[8];
    const float* be1 = (const float*)d_in[9];
    const float* W2 = (const float*)d_in[10];
    const float* b2 = (const float*)d_in[11];
    const float* g2 = (const float*)d_in[12];
    const float* be2 = (const float*)d_in[13];
    float* out = (float*)d_out;

    void *h1, *h2, *a1, *c1, *a2, *c2, *a3, *c3;
    void *p1s, *p1q, *p2s, *p2q, *p3s, *p3q;
    cudaGetSymbolAddress(&h1, g_h1);
    cudaGetSymbolAddress(&h2, g_h2);
    cudaGetSymbolAddress(&a1, g_a1);
    cudaGetSymbolAddress(&c1, g_c1);
    cudaGetSymbolAddress(&a2, g_a2);
    cudaGetSymbolAddress(&c2, g_c2);
    cudaGetSymbolAddress(&a3, g_a3);
    cudaGetSymbolAddress(&c3, g_c3);
    cudaGetSymbolAddress(&p1s, g_p1s);
    cudaGetSymbolAddress(&p1q, g_p1q);
    cudaGetSymbolAddress(&p2s, g_p2s);
    cudaGetSymbolAddress(&p2q, g_p2q);
    cudaGetSymbolAddress(&p3s, g_p3s);
    cudaGetSymbolAddress(&p3q, g_p3q);

    init_kernel<<<1, 32>>>();
    fused_fps_ball<<<NB + NB * NP, 512>>>(xyz, pts, W0, b0, out);
    comb_part<<<64, 256>>>((const float*)p1s, (const float*)p1q, g0, be0,
                           (float*)a1, (float*)c1, NQ);

    // launch #4 -> ncu profiles mlp2_kernel
    mlp2_kernel<<<MB2, 256>>>((const float*)h1, W1, b1,
                              (const float*)a1, (const float*)c1, (float*)h2);

    comb_part<<<64, 256>>>((const float*)p2s, (const float*)p2q, g1, be1,
                           (float*)a2, (float*)c2, MB2);

    mlp3_kernel<<<dim3(MB2, 2), 256>>>((const float*)h2, W2, b2,
                                       (const float*)a2, (const float*)c2);
    comb_part<<<128, 256>>>((const float*)p3s, (const float*)p3q, g2, be2,
                            (float*)a3, (float*)c3, MB2);
    final_kernel<<<NQ * 128 / 1024, 1024>>>(out);
}

// round 16
// speedup vs baseline: 1.3894x; 1.3894x over previous
#include <cuda_runtime.h>

#define NB 16
#define NPTS 4096
#define NP 512
#define NS 32
#define MROWS (NB*NP*NS)   // 262144 rows
#define NQ (NB*NP)         // 8192 queries
#define CAP 1024
#define MB2 1024           // mlp grid blocks (MROWS/256)

typedef unsigned long long u64;
typedef unsigned int u32;

// ---------------- scratch ----------------
__device__ float g_newxyz[NQ*3];
__device__ u32 g_prog[NB*32];
__device__ float g_h1[64*MROWS];
__device__ float g_h2[64*MROWS];
__device__ float g_p1s[64*NQ];
__device__ float g_p1q[64*NQ];
__device__ float g_p2s[64*MB2];
__device__ float g_p2q[64*MB2];
__device__ float g_p3s[128*MB2];
__device__ float g_p3q[128*MB2];
__device__ float g_hmax[NQ*128];
__device__ float g_a1[64], g_c1[64];
__device__ float g_a2[64], g_c2[64];
__device__ float g_a3[128], g_c3[128];

// ---------------- helpers ----------------
__device__ __forceinline__ u64 pk(float lo, float hi) {
    u64 r; asm("mov.b64 %0,{%1,%2};" : "=l"(r) : "f"(lo), "f"(hi)); return r;
}
__device__ __forceinline__ void upk(u64 v, float& lo, float& hi) {
    asm("mov.b64 {%0,%1},%2;" : "=f"(lo), "=f"(hi) : "l"(v));
}
__device__ __forceinline__ u64 addx2(u64 a, u64 b) {
    u64 r; asm("add.rn.f32x2 %0,%1,%2;" : "=l"(r) : "l"(a), "l"(b)); return r;
}
__device__ __forceinline__ u64 mulx2(u64 a, u64 b) {
    u64 r; asm("mul.rn.f32x2 %0,%1,%2;" : "=l"(r) : "l"(a), "l"(b)); return r;
}
__device__ __forceinline__ void fma2(u64& acc, u64 w, u64 x) {
    asm("fma.rn.f32x2 %0, %1, %2, %0;" : "+l"(acc) : "l"(w), "l"(x));
}
__device__ __forceinline__ u32 rmaxu(u32 v) {
    u32 r; asm("redux.sync.max.u32 %0,%1,0xffffffff;" : "=r"(r) : "r"(v)); return r;
}
__device__ __forceinline__ u32 rminu(u32 v) {
    u32 r; asm("redux.sync.min.u32 %0,%1,0xffffffff;" : "=r"(r) : "r"(v)); return r;
}
__device__ __forceinline__ u32 f2ord(float f) {
    u32 b = __float_as_uint(f);
    return b ^ (0x80000000u | (u32)((int)b >> 31));
}
__device__ __forceinline__ u32 uno(u32 u) {
    return (u & 0x80000000u) ? (u ^ 0x80000000u) : ~u;
}

// =======================================================================
__global__ void init_kernel() {
    if (threadIdx.x < NB) g_prog[threadIdx.x * 32] = 0u;
}

// =======================================================================
// FPS body (R13 proven form)
// =======================================================================
__device__ void fps_body(int b, const float* __restrict__ xyz,
                         float* __restrict__ out0,
                         u64 (*swk)[16], float4 (*swc)[16]) {
    const int tid = threadIdx.x, wid = tid >> 5, lid = tid & 31;
    const float* base = xyz + (size_t)b * 3 * NPTS;

    u64 xp[4], yp[4], zp[4];
    float dist[8];
#pragma unroll
    for (int k = 0; k < 4; k++) {
        int n0 = tid + 512 * (2 * k), n1 = n0 + 512;
        xp[k] = pk(base[n0], base[n1]);
        yp[k] = pk(base[NPTS + n0], base[NPTS + n1]);
        zp[k] = pk(base[2 * NPTS + n0], base[2 * NPTS + n1]);
        dist[2 * k] = 1e10f; dist[2 * k + 1] = 1e10f;
    }
    float cx = base[0], cy = base[NPTS], cz = base[2 * NPTS];

    for (int it = 0; it < NP; it++) {
        if (tid == 0) {
            g_newxyz[((size_t)b * NP + it) * 3 + 0] = cx;
            g_newxyz[((size_t)b * NP + it) * 3 + 1] = cy;
            g_newxyz[((size_t)b * NP + it) * 3 + 2] = cz;
            if (((it + 1) & 3) == 0) {
                asm volatile("st.release.gpu.global.u32 [%0], %1;"
                             :: "l"(&g_prog[b * 32]), "r"((u32)(it + 1)) : "memory");
            }
        }
        u64 ncx = pk(-cx, -cx), ncy = pk(-cy, -cy), ncz = pk(-cz, -cz);
        float bd = -1.0f;
#pragma unroll
        for (int k = 0; k < 4; k++) {
            u64 dx = addx2(xp[k], ncx);
            u64 dy = addx2(yp[k], ncy);
            u64 dz = addx2(zp[k], ncz);
            u64 d2 = addx2(addx2(mulx2(dx, dx), mulx2(dy, dy)), mulx2(dz, dz));
            float lo, hi; upk(d2, lo, hi);
            dist[2 * k] = fminf(dist[2 * k], lo);
            dist[2 * k + 1] = fminf(dist[2 * k + 1], hi);
            bd = fmaxf(bd, fmaxf(dist[2 * k], dist[2 * k + 1]));
        }
        int bj = 0;
#pragma unroll
        for (int j = 7; j >= 0; j--) if (dist[j] == bd) bj = j;
        u32 bi = (u32)(tid + 512 * bj);
        u32 bb = __float_as_uint(bd);
        u32 m = rmaxu(bb);
        u32 cand = (bb == m) ? bi : 0xffffffffu;
        u32 pmin = rminu(cand);
        const int par = it & 1;
        if (bb == m && bi == pmin) {
            float wx = 0.f, wy = 0.f, wz = 0.f;
#pragma unroll
            for (int k = 0; k < 4; k++) {
                float xl, xh, yl, yh, zl, zh;
                upk(xp[k], xl, xh); upk(yp[k], yl, yh); upk(zp[k], zl, zh);
                if (bj == 2 * k)     { wx = xl; wy = yl; wz = zl; }
                if (bj == 2 * k + 1) { wx = xh; wy = yh; wz = zh; }
            }
            swk[par][wid] = ((u64)m << 32) | (u32)(NPTS - 1 - pmin);
            swc[par][wid] = make_float4(wx, wy, wz, 0.f);
        }
        __syncthreads();
        u64 kk = swk[par][lid & 15];
        u32 h = (u32)(kk >> 32), l = (u32)kk;
        u32 m2 = rmaxu(h);
        u32 c2 = (h == m2) ? l : 0u;
        u32 l2 = rmaxu(c2);
        u32 slotc = (h == m2 && l == l2) ? (u32)(lid & 15) : 0xffffffffu;
        u32 slot = rminu(slotc);
        float4 w = swc[par][slot];
        cx = w.x; cy = w.y; cz = w.z;
    }

    __syncthreads();
    {
        const float* nx = g_newxyz + (size_t)b * NP * 3;
        out0[((size_t)b * 3 + 0) * NP + tid] = nx[tid * 3 + 0];
        out0[((size_t)b * 3 + 1) * NP + tid] = nx[tid * 3 + 1];
        out0[((size_t)b * 3 + 2) * NP + tid] = nx[tid * 3 + 2];
    }
}

// =======================================================================
// Ball body (R13 structure, unchanged)
// =======================================================================
__device__ void ball_body(int b, int s, const float* __restrict__ xyz,
                          const float* __restrict__ points,
                          const float* __restrict__ W0,
                          const float* __restrict__ b0,
                          u64* cand, u32* scnt, u64* gm, u64* sgmin, u64* sel,
                          float (*frow)[32], float (*Wsh)[64], float* bsh) {
    const int tid = threadIdx.x, wid = tid >> 5, lid = tid & 31;
    const int q = b * NP + s;
    const float* base = xyz + (size_t)b * 3 * NPTS;
    const u32 uth = f2ord(0.04f);

    for (int i = tid; i < 9 * 64; i += 512) {
        int c = i / 64, o = i % 64;
        Wsh[c][o] = W0[o * 9 + c];
    }
    if (tid < 64) bsh[tid] = b0[tid];
    if (tid == 0) *scnt = 0u;

    u64 xp[4], yp[4], zp[4], pnp[4];
#pragma unroll
    for (int k = 0; k < 4; k++) {
        int n0 = tid + 512 * (2 * k), n1 = n0 + 512;
        xp[k] = pk(base[n0], base[n1]);
        yp[k] = pk(base[NPTS + n0], base[NPTS + n1]);
        zp[k] = pk(base[2 * NPTS + n0], base[2 * NPTS + n1]);
        pnp[k] = addx2(addx2(mulx2(xp[k], xp[k]), mulx2(yp[k], yp[k])),
                       mulx2(zp[k], zp[k]));
    }

    if (tid == 0) {
        u32 p;
        while (true) {
            asm volatile("ld.acquire.gpu.global.u32 %0,[%1];"
                         : "=r"(p) : "l"(&g_prog[b * 32]) : "memory");
            if (p > (u32)s) break;
            __nanosleep(64);
        }
    }
    __syncthreads();

    const float qx = g_newxyz[(size_t)q * 3 + 0];
    const float qy = g_newxyz[(size_t)q * 3 + 1];
    const float qz = g_newxyz[(size_t)q * 3 + 2];
    const float qn = __fadd_rn(__fadd_rn(__fmul_rn(qx, qx), __fmul_rn(qy, qy)),
                               __fmul_rn(qz, qz));
    u64 qxp = pk(qx, qx), qyp = pk(qy, qy), qzp = pk(qz, qz);
    u64 qnp = pk(qn, qn), n2p = pk(-2.0f, -2.0f);

    u64 key[8];
    u32 mask = 0, myCnt = 0;
    u64 loc = ~0ull;
#pragma unroll
    for (int k = 0; k < 4; k++) {
        u64 dt = addx2(addx2(mulx2(xp[k], qxp), mulx2(yp[k], qyp)),
                       mulx2(zp[k], qzp));
        u64 d = addx2(addx2(qnp, pnp[k]), mulx2(dt, n2p));
        float lo, hi; upk(d, lo, hi);
        int n0 = tid + 512 * (2 * k);
        u64 k0 = ((u64)f2ord(lo) << 32) | (u32)n0;
        u64 k1 = ((u64)f2ord(hi) << 32) | (u32)(n0 + 512);
        key[2 * k] = k0; key[2 * k + 1] = k1;
        u64 mn = (k0 < k1) ? k0 : k1;
        loc = (mn < loc) ? mn : loc;
        if ((u32)(k0 >> 32) <= uth) { mask |= 1u << (2 * k);     myCnt++; }
        if ((u32)(k1 >> 32) <= uth) { mask |= 1u << (2 * k + 1); myCnt++; }
    }

    u32 pre = myCnt;
#pragma unroll
    for (int off = 1; off < 32; off <<= 1) {
        u32 v = __shfl_up_sync(0xffffffffu, pre, off);
        if (lid >= off) pre += v;
    }
    u32 wtot = __shfl_sync(0xffffffffu, pre, 31);
    u32 wb = 0;
    if (lid == 31) wb = atomicAdd(scnt, wtot);
    wb = __shfl_sync(0xffffffffu, wb, 31);
    u32 pos = wb + pre - myCnt;
#pragma unroll
    for (int j = 0; j < 8; j++)
        if ((mask >> j) & 1) { if (pos < CAP) cand[pos] = key[j]; pos++; }

    {
        u32 hi = (u32)(loc >> 32);
        u32 m = rminu(hi);
        u32 c = (hi == m) ? (u32)loc : 0xffffffffu;
        u32 nm = rminu(c);
        if (lid == 0) gm[wid] = ((u64)m << 32) | nm;
    }
    __syncthreads();

    if (wid == 0) {
        u64 v = gm[lid & 15];
        u32 h2 = (u32)(v >> 32);
        u32 m2 = rminu(h2);
        u32 c2 = (h2 == m2) ? (u32)v : 0xffffffffu;
        u32 n2 = rminu(c2);
        if (lid == 0) *sgmin = ((u64)m2 << 32) | n2;

        u32 count = *scnt;
        if (count > CAP) count = CAP;
        int nslots = (int)((count + 31) >> 5);
        u64 loc0 = ~0ull;
        for (int j = 0; j < nslots; j++) {
            u32 p = (u32)lid + 32u * j;
            u64 kv = (p < count) ? cand[p] : ~0ull;
            loc0 = (kv < loc0) ? kv : loc0;
        }
        for (int k = 0; k < NS; k++) {
            u32 hi = (u32)(loc0 >> 32);
            u32 m = rminu(hi);
            u32 cd = (hi == m) ? (u32)loc0 : 0xffffffffu;
            u32 nm = rminu(cd);
            u64 wkey = ((u64)m << 32) | nm;
            if (lid == 0) sel[k] = wkey;
            if (loc0 == wkey && wkey != ~0ull) {
                loc0 = ~0ull;
                for (int j = 0; j < nslots; j++) {
                    u32 p = (u32)lid + 32u * j;
                    if (p < count) {
                        u64 kv = cand[p];
                        if (kv == wkey) { cand[p] = ~0ull; kv = ~0ull; }
                        loc0 = (kv < loc0) ? kv : loc0;
                    }
                }
            }
        }
    }
    __syncthreads();

    if (tid < NS) {
        u64 kk = sel[tid];
        u32 wd = (u32)(kk >> 32);
        u32 first_n = (u32)(*sgmin & 0xffffffffu);
        u32 idx = (wd > uth) ? first_n : (u32)(kk & 0xffffffffu);
        float x = base[idx], y = base[NPTS + idx], z = base[2 * NPTS + idx];
        frow[0][tid] = x - qx;
        frow[1][tid] = y - qy;
        frow[2][tid] = z - qz;
        const float* pb = points + (size_t)b * 6 * NPTS;
#pragma unroll
        for (int d = 0; d < 6; d++) frow[3 + d][tid] = pb[(size_t)d * NPTS + idx];
    }
    __syncthreads();

    {
        const int r = lid, og = wid;
        float acc[4];
#pragma unroll
        for (int i = 0; i < 4; i++) acc[i] = bsh[og * 4 + i];
#pragma unroll
        for (int c = 0; c < 9; c++) {
            float f = frow[c][r];
#pragma unroll
            for (int i = 0; i < 4; i++) acc[i] = fmaf(Wsh[c][og * 4 + i], f, acc[i]);
        }
        float* hb = g_h1 + (size_t)q * NS + r;
#pragma unroll
        for (int i = 0; i < 4; i++) hb[(size_t)(og * 4 + i) * MROWS] = acc[i];

        float sv[4], qv[4];
#pragma unroll
        for (int i = 0; i < 4; i++) {
            sv[i] = acc[i];
            qv[i] = acc[i] * acc[i];
#pragma unroll
            for (int off = 1; off < 32; off <<= 1) {
                sv[i] += __shfl_xor_sync(0xffffffffu, sv[i], off);
                qv[i] += __shfl_xor_sync(0xffffffffu, qv[i], off);
            }
        }
        if (lid == 0) {
#pragma unroll
            for (int i = 0; i < 4; i++) {
                g_p1s[(size_t)(og * 4 + i) * NQ + q] = sv[i];
                g_p1q[(size_t)(og * 4 + i) * NQ + q] = qv[i];
            }
        }
    }
}

__global__ void __launch_bounds__(512, 2) fused_fps_ball(const float* __restrict__ xyz,
                                                         const float* __restrict__ points,
                                                         const float* __restrict__ W0,
                                                         const float* __restrict__ b0,
                                                         float* __restrict__ out0) {
    __shared__ u64 swk[2][16];
    __shared__ float4 swc[2][16];
    __shared__ u64 cand[CAP];
    __shared__ u32 scnt;
    __shared__ u64 gm[16];
    __shared__ u64 sgmin;
    __shared__ u64 sel[NS];
    __shared__ float frow[9][32];
    __shared__ float Wsh[9][64];
    __shared__ float bsh[64];

    const int bid = blockIdx.x;
    if (bid < NB) {
        fps_body(bid, xyz, out0, swk, swc);
    } else {
        int b, s;
        if (bid >= 148 && bid < 148 + NB) {
            s = NP - 1; b = bid - 148;
        } else {
            int idx = (bid < 148) ? (bid - NB) : (bid - 2 * NB);
            b = idx & 15; s = idx >> 4;
        }
        ball_body(b, s, xyz, points, W0, b0,
                  cand, &scnt, gm, &sgmin, sel, frow, Wsh, bsh);
    }
}

// =======================================================================
// comb_part: BN coeffs from per-channel partial arrays (stride n).
// =======================================================================
__global__ void __launch_bounds__(256) comb_part(const float* __restrict__ ps,
                                                 const float* __restrict__ pq,
                                                 const float* __restrict__ g,
                                                 const float* __restrict__ be,
                                                 float* __restrict__ a,
                                                 float* __restrict__ c, int n) {
    const int ch = blockIdx.x, tid = threadIdx.x;
    const float* s0 = ps + (size_t)ch * n;
    const float* q0 = pq + (size_t)ch * n;
    float s = 0.f, s2 = 0.f;
    for (int i = tid; i < n; i += 256) { s += s0[i]; s2 += q0[i]; }
    __shared__ float sh[256], sh2[256];
    sh[tid] = s; sh2[tid] = s2;
    __syncthreads();
    for (int off = 128; off > 0; off >>= 1) {
        if (tid < off) { sh[tid] += sh[tid + off]; sh2[tid] += sh2[tid + off]; }
        __syncthreads();
    }
    if (tid == 0) {
        double mean = (double)sh[0] / (double)MROWS;
        double var = (double)sh2[0] / (double)MROWS - mean * mean;
        double af = (double)g[ch] / sqrt(var + 1e-5);
        a[ch] = (float)af;
        c[ch] = (float)((double)be[ch] - mean * af);
    }
}

// =======================================================================
// MLP layer 2 (64->64), 512 thr: thread = 2 rows x 16 channels (16 accs).
// quarter = tid>>7 selects channel quarter (warp-uniform -> broadcast LDS).
// =======================================================================
__global__ void __launch_bounds__(512, 2) mlp2_kernel(const float* __restrict__ in,
                                                      const float* __restrict__ W,
                                                      const float* __restrict__ bias,
                                                      const float* __restrict__ aP,
                                                      const float* __restrict__ cP,
                                                      float* __restrict__ out) {
    __shared__ __align__(16) float Wsh[64][64];
    __shared__ float bsh[64], ash[64], csh[64];
    __shared__ u64 sS[16][8], sQ[16][8];
    const int tid = threadIdx.x, wid = tid >> 5, lid = tid & 31;
    const int rt = tid & 127, quarter = tid >> 7;
    const int o0 = quarter * 16;

    for (int i = tid; i < 64 * 64; i += 512) {
        int c = i >> 6, o = i & 63;
        Wsh[c][o] = W[(size_t)o * 64 + c];
    }
    if (tid < 64) { bsh[tid] = bias[tid]; ash[tid] = aP[tid]; csh[tid] = cP[tid]; }
    __syncthreads();

    const size_t r0 = (size_t)blockIdx.x * 256 + rt;
    const float* inr = in + r0;

    u64 acc[16];
#pragma unroll
    for (int k = 0; k < 8; k++) {
        u64 bb = pk(bsh[o0 + 2 * k], bsh[o0 + 2 * k + 1]);
        acc[k] = bb; acc[8 + k] = bb;
    }

#pragma unroll 8
    for (int c = 0; c < 64; c++) {
        float xa = inr[(size_t)c * MROWS];
        float xb = inr[(size_t)c * MROWS + 128];
        float av = ash[c], cv = csh[c];
        xa = fmaxf(fmaf(av, xa, cv), 0.0f);
        xb = fmaxf(fmaf(av, xb, cv), 0.0f);
        u64 x0 = pk(xa, xa), x1 = pk(xb, xb);
        const ulonglong2* w4 = reinterpret_cast<const ulonglong2*>(&Wsh[c][o0]);
#pragma unroll
        for (int k4 = 0; k4 < 4; k4++) {
            ulonglong2 w = w4[k4];
            fma2(acc[2 * k4 + 0], w.x, x0);
            fma2(acc[2 * k4 + 1], w.y, x0);
            fma2(acc[8 + 2 * k4 + 0], w.x, x1);
            fma2(acc[8 + 2 * k4 + 1], w.y, x1);
        }
    }

    float* outr = out + r0;
#pragma unroll
    for (int k = 0; k < 8; k++) {
        float lo, hi;
        upk(acc[k], lo, hi);
        outr[(size_t)(o0 + 2 * k) * MROWS] = lo;
        outr[(size_t)(o0 + 2 * k + 1) * MROWS] = hi;
        upk(acc[8 + k], lo, hi);
        outr[(size_t)(o0 + 2 * k) * MROWS + 128] = lo;
        outr[(size_t)(o0 + 2 * k + 1) * MROWS + 128] = hi;
    }

    // per-block stat partials: warp covers 64 rows x 16 channels
#pragma unroll
    for (int k = 0; k < 8; k++) {
        u64 sv = addx2(acc[k], acc[8 + k]);
        u64 qv = addx2(mulx2(acc[k], acc[k]), mulx2(acc[8 + k], acc[8 + k]));
#pragma unroll
        for (int off = 1; off < 32; off <<= 1) {
            sv = addx2(sv, __shfl_xor_sync(0xffffffffu, sv, off));
            qv = addx2(qv, __shfl_xor_sync(0xffffffffu, qv, off));
        }
        if (lid == 0) { sS[wid][k] = sv; sQ[wid][k] = qv; }
    }
    __syncthreads();
    if (tid < 128) {
        int ch = tid & 63;
        bool isq = tid >= 64;
        int qc = ch >> 4, k = (ch & 15) >> 1, lohi = ch & 1;
        const u64 (*src)[8] = isq ? sQ : sS;
        u64 t = src[4 * qc][k];
#pragma unroll
        for (int w = 1; w < 4; w++) t = addx2(t, src[4 * qc + w][k]);
        float lo, hi; upk(t, lo, hi);
        (isq ? g_p2q : g_p2s)[(size_t)ch * MB2 + blockIdx.x] = lohi ? hi : lo;
    }
}

// =======================================================================
// MLP layer 3 (64->128 via y-halves), 512 thr, 16 accs, NO h3 store.
// Epilogue: stat partials + per-query channel max (warp = 1 query x 16ch).
// =======================================================================
__global__ void __launch_bounds__(512, 2) mlp3_kernel(const float* __restrict__ in,
                                                      const float* __restrict__ W,
                                                      const float* __restrict__ bias,
                                                      const float* __restrict__ aP,
                                                      const float* __restrict__ cP) {
    __shared__ __align__(16) float Wsh[64][64];
    __shared__ float bsh[64], ash[64], csh[64];
    __shared__ u64 sS[16][8], sQ[16][8];
    const int tid = threadIdx.x, wid = tid >> 5, lid = tid & 31;
    const int rt = tid & 127, quarter = tid >> 7;
    const int o0 = quarter * 16;
    const int ocb = blockIdx.y * 64;

    for (int i = tid; i < 64 * 64; i += 512) {
        int c = i >> 6, o = i & 63;
        Wsh[c][o] = W[(size_t)(ocb + o) * 64 + c];
    }
    if (tid < 64) { bsh[tid] = bias[ocb + tid]; ash[tid] = aP[tid]; csh[tid] = cP[tid]; }
    __syncthreads();

    const size_t r0 = (size_t)blockIdx.x * 256 + rt;
    const float* inr = in + r0;

    u64 acc[16];
#pragma unroll
    for (int k = 0; k < 8; k++) {
        u64 bb = pk(bsh[o0 + 2 * k], bsh[o0 + 2 * k + 1]);
        acc[k] = bb; acc[8 + k] = bb;
    }

#pragma unroll 8
    for (int c = 0; c < 64; c++) {
        float xa = inr[(size_t)c * MROWS];
        float xb = inr[(size_t)c * MROWS + 128];
        float av = ash[c], cv = csh[c];
        xa = fmaxf(fmaf(av, xa, cv), 0.0f);
        xb = fmaxf(fmaf(av, xb, cv), 0.0f);
        u64 x0 = pk(xa, xa), x1 = pk(xb, xb);
        const ulonglong2* w4 = reinterpret_cast<const ulonglong2*>(&Wsh[c][o0]);
#pragma unroll
        for (int k4 = 0; k4 < 4; k4++) {
            ulonglong2 w = w4[k4];
            fma2(acc[2 * k4 + 0], w.x, x0);
            fma2(acc[2 * k4 + 1], w.y, x0);
            fma2(acc[8 + 2 * k4 + 0], w.x, x1);
            fma2(acc[8 + 2 * k4 + 1], w.y, x1);
        }
    }

    // stat partials
#pragma unroll
    for (int k = 0; k < 8; k++) {
        u64 sv = addx2(acc[k], acc[8 + k]);
        u64 qv = addx2(mulx2(acc[k], acc[k]), mulx2(acc[8 + k], acc[8 + k]));
#pragma unroll
        for (int off = 1; off < 32; off <<= 1) {
            sv = addx2(sv, __shfl_xor_sync(0xffffffffu, sv, off));
            qv = addx2(qv, __shfl_xor_sync(0xffffffffu, qv, off));
        }
        if (lid == 0) { sS[wid][k] = sv; sQ[wid][k] = qv; }
    }

    // hmax: warp lanes = 32 consecutive rows = one query (x2 row halves)
    {
        const int qa = blockIdx.x * 8 + (wid & 3);
        const int qb = qa + 4;
        const int cb2 = (ocb + o0) >> 1;
        float2* hmax2 = reinterpret_cast<float2*>(g_hmax);
#pragma unroll
        for (int k = 0; k < 8; k++) {
            float lo, hi;
            upk(acc[k], lo, hi);
            u32 a0 = rmaxu(f2ord(lo)), b0v = rmaxu(f2ord(hi));
            upk(acc[8 + k], lo, hi);
            u32 a1 = rmaxu(f2ord(lo)), b1v = rmaxu(f2ord(hi));
            if (lid == 0) {
                hmax2[(size_t)qa * 64 + cb2 + k] =
                    make_float2(__uint_as_float(uno(a0)), __uint_as_float(uno(b0v)));
                hmax2[(size_t)qb * 64 + cb2 + k] =
                    make_float2(__uint_as_float(uno(a1)), __uint_as_float(uno(b1v)));
            }
        }
    }
    __syncthreads();
    if (tid < 128) {
        int ch = tid & 63;
        bool isq = tid >= 64;
        int qc = ch >> 4, k = (ch & 15) >> 1, lohi = ch & 1;
        const u64 (*src)[8] = isq ? sQ : sS;
        u64 t = src[4 * qc][k];
#pragma unroll
        for (int w = 1; w < 4; w++) t = addx2(t, src[4 * qc + w][k]);
        float lo, hi; upk(t, lo, hi);
        (isq ? g_p3q : g_p3s)[(size_t)(ocb + ch) * MB2 + blockIdx.x] = lohi ? hi : lo;
    }
}

// =======================================================================
// final: out = relu(a3*hmax + c3)  (a3>0 so max commutes exactly)
// =======================================================================
__global__ void __launch_bounds__(1024) final_kernel(float* __restrict__ out) {
    const int t = blockIdx.x * 1024 + threadIdx.x;
    const int q = t >> 7, o = t & 127;
    float v = g_hmax[t];
    float y = fmaxf(fmaf(g_a3[o], v, g_c3[o]), 0.0f);
    const int b = q >> 9, s = q & 511;
    out[(size_t)NB * 3 * NP + (((size_t)b * 128 + o) << 9) + s] = y;
}

// ---------------- launch ----------------
extern "C" void kernel_launch(void* const* d_in, const int* in_sizes, int n_in,
                              void* d_out, int out_size) {
    const float* xyz = (const float*)d_in[0];
    const float* pts = (const float*)d_in[1];
    const float* W0 = (const float*)d_in[2];
    const float* b0 = (const float*)d_in[3];
    const float* g0 = (const float*)d_in[4];
    const float* be0 = (const float*)d_in[5];
    const float* W1 = (const float*)d_in[6];
    const float* b1 = (const float*)d_in[7];
    const float* g1 = (const float*)d_in[8];
    const float* be1 = (const float*)d_in[9];
    const float* W2 = (const float*)d_in[10];
    const float* b2 = (const float*)d_in[11];
    const float* g2 = (const float*)d_in[12];
    const float* be2 = (const float*)d_in[13];
    float* out = (float*)d_out;

    void *h1, *h2, *a1, *c1, *a2, *c2, *a3, *c3;
    void *p1s, *p1q, *p2s, *p2q, *p3s, *p3q;
    cudaGetSymbolAddress(&h1, g_h1);
    cudaGetSymbolAddress(&h2, g_h2);
    cudaGetSymbolAddress(&a1, g_a1);
    cudaGetSymbolAddress(&c1, g_c1);
    cudaGetSymbolAddress(&a2, g_a2);
    cudaGetSymbolAddress(&c2, g_c2);
    cudaGetSymbolAddress(&a3, g_a3);
    cudaGetSymbolAddress(&c3, g_c3);
    cudaGetSymbolAddress(&p1s, g_p1s);
    cudaGetSymbolAddress(&p1q, g_p1q);
    cudaGetSymbolAddress(&p2s, g_p2s);
    cudaGetSymbolAddress(&p2q, g_p2q);
    cudaGetSymbolAddress(&p3s, g_p3s);
    cudaGetSymbolAddress(&p3q, g_p3q);

    init_kernel<<<1, 32>>>();
    fused_fps_ball<<<NB + NB * NP, 512>>>(xyz, pts, W0, b0, out);
    comb_part<<<64, 256>>>((const float*)p1s, (const float*)p1q, g0, be0,
                           (float*)a1, (float*)c1, NQ);

    // launch #4 -> ncu profiles mlp2_kernel
    mlp2_kernel<<<MB2, 512>>>((const float*)h1, W1, b1,
                              (const float*)a1, (const float*)c1, (float*)h2);

    comb_part<<<64, 256>>>((const float*)p2s, (const float*)p2q, g1, be1,
                           (float*)a2, (float*)c2, MB2);

    mlp3_kernel<<<dim3(MB2, 2), 512>>>((const float*)h2, W2, b2,
                                       (const float*)a2, (const float*)c2);
    comb_part<<<128, 256>>>((const float*)p3s, (const float*)p3q, g2, be2,
                            (float*)a3, (float*)c3, MB2);
    final_kernel<<<NQ * 128 / 1024, 1024>>>(out);
}

// round 17
// speedup vs baseline: 1.4544x; 1.0468x over previous
#include <cuda_runtime.h>

#define NB 16
#define NPTS 4096
#define NP 512
#define NS 32
#define MROWS (NB*NP*NS)   // 262144 rows
#define NQ (NB*NP)         // 8192 queries
#define CAP 1024
#define MB2 1024           // mlp grid blocks (MROWS/256)

typedef unsigned long long u64;
typedef unsigned int u32;

// ---------------- scratch ----------------
__device__ float g_newxyz[NQ*3];
__device__ u32 g_prog[NB*32];
__device__ float g_h1[64*MROWS];
__device__ float g_h2[64*MROWS];
__device__ float g_p1s[64*NQ];
__device__ float g_p1q[64*NQ];
__device__ float g_p2s[64*MB2];
__device__ float g_p2q[64*MB2];
__device__ float g_p3s[128*MB2];
__device__ float g_p3q[128*MB2];
__device__ float g_hmax[NQ*128];
__device__ float g_a1[64], g_c1[64];
__device__ float g_a2[64], g_c2[64];
__device__ float g_a3[128], g_c3[128];

// ---------------- helpers ----------------
__device__ __forceinline__ u64 pk(float lo, float hi) {
    u64 r; asm("mov.b64 %0,{%1,%2};" : "=l"(r) : "f"(lo), "f"(hi)); return r;
}
__device__ __forceinline__ void upk(u64 v, float& lo, float& hi) {
    asm("mov.b64 {%0,%1},%2;" : "=f"(lo), "=f"(hi) : "l"(v));
}
__device__ __forceinline__ u64 addx2(u64 a, u64 b) {
    u64 r; asm("add.rn.f32x2 %0,%1,%2;" : "=l"(r) : "l"(a), "l"(b)); return r;
}
__device__ __forceinline__ u64 mulx2(u64 a, u64 b) {
    u64 r; asm("mul.rn.f32x2 %0,%1,%2;" : "=l"(r) : "l"(a), "l"(b)); return r;
}
__device__ __forceinline__ void fma2(u64& acc, u64 w, u64 x) {
    asm("fma.rn.f32x2 %0, %1, %2, %0;" : "+l"(acc) : "l"(w), "l"(x));
}
__device__ __forceinline__ u32 rmaxu(u32 v) {
    u32 r; asm("redux.sync.max.u32 %0,%1,0xffffffff;" : "=r"(r) : "r"(v)); return r;
}
__device__ __forceinline__ u32 rminu(u32 v) {
    u32 r; asm("redux.sync.min.u32 %0,%1,0xffffffff;" : "=r"(r) : "r"(v)); return r;
}
__device__ __forceinline__ u32 f2ord(float f) {
    u32 b = __float_as_uint(f);
    return b ^ (0x80000000u | (u32)((int)b >> 31));
}
__device__ __forceinline__ u32 uno(u32 u) {
    return (u & 0x80000000u) ? (u ^ 0x80000000u) : ~u;
}

// =======================================================================
__global__ void init_kernel() {
    if (threadIdx.x < NB) g_prog[threadIdx.x * 32] = 0u;
}

// =======================================================================
// FPS body (R13 proven form)
// =======================================================================
__device__ void fps_body(int b, const float* __restrict__ xyz,
                         float* __restrict__ out0,
                         u64 (*swk)[16], float4 (*swc)[16]) {
    const int tid = threadIdx.x, wid = tid >> 5, lid = tid & 31;
    const float* base = xyz + (size_t)b * 3 * NPTS;

    u64 xp[4], yp[4], zp[4];
    float dist[8];
#pragma unroll
    for (int k = 0; k < 4; k++) {
        int n0 = tid + 512 * (2 * k), n1 = n0 + 512;
        xp[k] = pk(base[n0], base[n1]);
        yp[k] = pk(base[NPTS + n0], base[NPTS + n1]);
        zp[k] = pk(base[2 * NPTS + n0], base[2 * NPTS + n1]);
        dist[2 * k] = 1e10f; dist[2 * k + 1] = 1e10f;
    }
    float cx = base[0], cy = base[NPTS], cz = base[2 * NPTS];

    for (int it = 0; it < NP; it++) {
        if (tid == 0) {
            g_newxyz[((size_t)b * NP + it) * 3 + 0] = cx;
            g_newxyz[((size_t)b * NP + it) * 3 + 1] = cy;
            g_newxyz[((size_t)b * NP + it) * 3 + 2] = cz;
            if (((it + 1) & 3) == 0) {
                asm volatile("st.release.gpu.global.u32 [%0], %1;"
                             :: "l"(&g_prog[b * 32]), "r"((u32)(it + 1)) : "memory");
            }
        }
        u64 ncx = pk(-cx, -cx), ncy = pk(-cy, -cy), ncz = pk(-cz, -cz);
        float bd = -1.0f;
#pragma unroll
        for (int k = 0; k < 4; k++) {
            u64 dx = addx2(xp[k], ncx);
            u64 dy = addx2(yp[k], ncy);
            u64 dz = addx2(zp[k], ncz);
            u64 d2 = addx2(addx2(mulx2(dx, dx), mulx2(dy, dy)), mulx2(dz, dz));
            float lo, hi; upk(d2, lo, hi);
            dist[2 * k] = fminf(dist[2 * k], lo);
            dist[2 * k + 1] = fminf(dist[2 * k + 1], hi);
            bd = fmaxf(bd, fmaxf(dist[2 * k], dist[2 * k + 1]));
        }
        int bj = 0;
#pragma unroll
        for (int j = 7; j >= 0; j--) if (dist[j] == bd) bj = j;
        u32 bi = (u32)(tid + 512 * bj);
        u32 bb = __float_as_uint(bd);
        u32 m = rmaxu(bb);
        u32 cand = (bb == m) ? bi : 0xffffffffu;
        u32 pmin = rminu(cand);
        const int par = it & 1;
        if (bb == m && bi == pmin) {
            float wx = 0.f, wy = 0.f, wz = 0.f;
#pragma unroll
            for (int k = 0; k < 4; k++) {
                float xl, xh, yl, yh, zl, zh;
                upk(xp[k], xl, xh); upk(yp[k], yl, yh); upk(zp[k], zl, zh);
                if (bj == 2 * k)     { wx = xl; wy = yl; wz = zl; }
                if (bj == 2 * k + 1) { wx = xh; wy = yh; wz = zh; }
            }
            swk[par][wid] = ((u64)m << 32) | (u32)(NPTS - 1 - pmin);
            swc[par][wid] = make_float4(wx, wy, wz, 0.f);
        }
        __syncthreads();
        u64 kk = swk[par][lid & 15];
        u32 h = (u32)(kk >> 32), l = (u32)kk;
        u32 m2 = rmaxu(h);
        u32 c2 = (h == m2) ? l : 0u;
        u32 l2 = rmaxu(c2);
        u32 slotc = (h == m2 && l == l2) ? (u32)(lid & 15) : 0xffffffffu;
        u32 slot = rminu(slotc);
        float4 w = swc[par][slot];
        cx = w.x; cy = w.y; cz = w.z;
    }

    __syncthreads();
    {
        const float* nx = g_newxyz + (size_t)b * NP * 3;
        out0[((size_t)b * 3 + 0) * NP + tid] = nx[tid * 3 + 0];
        out0[((size_t)b * 3 + 1) * NP + tid] = nx[tid * 3 + 1];
        out0[((size_t)b * 3 + 2) * NP + tid] = nx[tid * 3 + 2];
    }
}

// =======================================================================
// Ball body (R13 structure, unchanged)
// =======================================================================
__device__ void ball_body(int b, int s, const float* __restrict__ xyz,
                          const float* __restrict__ points,
                          const float* __restrict__ W0,
                          const float* __restrict__ b0,
                          u64* cand, u32* scnt, u64* gm, u64* sgmin, u64* sel,
                          float (*frow)[32], float (*Wsh)[64], float* bsh) {
    const int tid = threadIdx.x, wid = tid >> 5, lid = tid & 31;
    const int q = b * NP + s;
    const float* base = xyz + (size_t)b * 3 * NPTS;
    const u32 uth = f2ord(0.04f);

    for (int i = tid; i < 9 * 64; i += 512) {
        int c = i / 64, o = i % 64;
        Wsh[c][o] = W0[o * 9 + c];
    }
    if (tid < 64) bsh[tid] = b0[tid];
    if (tid == 0) *scnt = 0u;

    u64 xp[4], yp[4], zp[4], pnp[4];
#pragma unroll
    for (int k = 0; k < 4; k++) {
        int n0 = tid + 512 * (2 * k), n1 = n0 + 512;
        xp[k] = pk(base[n0], base[n1]);
        yp[k] = pk(base[NPTS + n0], base[NPTS + n1]);
        zp[k] = pk(base[2 * NPTS + n0], base[2 * NPTS + n1]);
        pnp[k] = addx2(addx2(mulx2(xp[k], xp[k]), mulx2(yp[k], yp[k])),
                       mulx2(zp[k], zp[k]));
    }

    if (tid == 0) {
        u32 p;
        while (true) {
            asm volatile("ld.acquire.gpu.global.u32 %0,[%1];"
                         : "=r"(p) : "l"(&g_prog[b * 32]) : "memory");
            if (p > (u32)s) break;
            __nanosleep(64);
        }
    }
    __syncthreads();

    const float qx = g_newxyz[(size_t)q * 3 + 0];
    const float qy = g_newxyz[(size_t)q * 3 + 1];
    const float qz = g_newxyz[(size_t)q * 3 + 2];
    const float qn = __fadd_rn(__fadd_rn(__fmul_rn(qx, qx), __fmul_rn(qy, qy)),
                               __fmul_rn(qz, qz));
    u64 qxp = pk(qx, qx), qyp = pk(qy, qy), qzp = pk(qz, qz);
    u64 qnp = pk(qn, qn), n2p = pk(-2.0f, -2.0f);

    u64 key[8];
    u32 mask = 0, myCnt = 0;
    u64 loc = ~0ull;
#pragma unroll
    for (int k = 0; k < 4; k++) {
        u64 dt = addx2(addx2(mulx2(xp[k], qxp), mulx2(yp[k], qyp)),
                       mulx2(zp[k], qzp));
        u64 d = addx2(addx2(qnp, pnp[k]), mulx2(dt, n2p));
        float lo, hi; upk(d, lo, hi);
        int n0 = tid + 512 * (2 * k);
        u64 k0 = ((u64)f2ord(lo) << 32) | (u32)n0;
        u64 k1 = ((u64)f2ord(hi) << 32) | (u32)(n0 + 512);
        key[2 * k] = k0; key[2 * k + 1] = k1;
        u64 mn = (k0 < k1) ? k0 : k1;
        loc = (mn < loc) ? mn : loc;
        if ((u32)(k0 >> 32) <= uth) { mask |= 1u << (2 * k);     myCnt++; }
        if ((u32)(k1 >> 32) <= uth) { mask |= 1u << (2 * k + 1); myCnt++; }
    }

    u32 pre = myCnt;
#pragma unroll
    for (int off = 1; off < 32; off <<= 1) {
        u32 v = __shfl_up_sync(0xffffffffu, pre, off);
        if (lid >= off) pre += v;
    }
    u32 wtot = __shfl_sync(0xffffffffu, pre, 31);
    u32 wb = 0;
    if (lid == 31) wb = atomicAdd(scnt, wtot);
    wb = __shfl_sync(0xffffffffu, wb, 31);
    u32 pos = wb + pre - myCnt;
#pragma unroll
    for (int j = 0; j < 8; j++)
        if ((mask >> j) & 1) { if (pos < CAP) cand[pos] = key[j]; pos++; }

    {
        u32 hi = (u32)(loc >> 32);
        u32 m = rminu(hi);
        u32 c = (hi == m) ? (u32)loc : 0xffffffffu;
        u32 nm = rminu(c);
        if (lid == 0) gm[wid] = ((u64)m << 32) | nm;
    }
    __syncthreads();

    if (wid == 0) {
        u64 v = gm[lid & 15];
        u32 h2 = (u32)(v >> 32);
        u32 m2 = rminu(h2);
        u32 c2 = (h2 == m2) ? (u32)v : 0xffffffffu;
        u32 n2 = rminu(c2);
        if (lid == 0) *sgmin = ((u64)m2 << 32) | n2;

        u32 count = *scnt;
        if (count > CAP) count = CAP;
        int nslots = (int)((count + 31) >> 5);
        u64 loc0 = ~0ull;
        for (int j = 0; j < nslots; j++) {
            u32 p = (u32)lid + 32u * j;
            u64 kv = (p < count) ? cand[p] : ~0ull;
            loc0 = (kv < loc0) ? kv : loc0;
        }
        for (int k = 0; k < NS; k++) {
            u32 hi = (u32)(loc0 >> 32);
            u32 m = rminu(hi);
            u32 cd = (hi == m) ? (u32)loc0 : 0xffffffffu;
            u32 nm = rminu(cd);
            u64 wkey = ((u64)m << 32) | nm;
            if (lid == 0) sel[k] = wkey;
            if (loc0 == wkey && wkey != ~0ull) {
                loc0 = ~0ull;
                for (int j = 0; j < nslots; j++) {
                    u32 p = (u32)lid + 32u * j;
                    if (p < count) {
                        u64 kv = cand[p];
                        if (kv == wkey) { cand[p] = ~0ull; kv = ~0ull; }
                        loc0 = (kv < loc0) ? kv : loc0;
                    }
                }
            }
        }
    }
    __syncthreads();

    if (tid < NS) {
        u64 kk = sel[tid];
        u32 wd = (u32)(kk >> 32);
        u32 first_n = (u32)(*sgmin & 0xffffffffu);
        u32 idx = (wd > uth) ? first_n : (u32)(kk & 0xffffffffu);
        float x = base[idx], y = base[NPTS + idx], z = base[2 * NPTS + idx];
        frow[0][tid] = x - qx;
        frow[1][tid] = y - qy;
        frow[2][tid] = z - qz;
        const float* pb = points + (size_t)b * 6 * NPTS;
#pragma unroll
        for (int d = 0; d < 6; d++) frow[3 + d][tid] = pb[(size_t)d * NPTS + idx];
    }
    __syncthreads();

    {
        const int r = lid, og = wid;
        float acc[4];
#pragma unroll
        for (int i = 0; i < 4; i++) acc[i] = bsh[og * 4 + i];
#pragma unroll
        for (int c = 0; c < 9; c++) {
            float f = frow[c][r];
#pragma unroll
            for (int i = 0; i < 4; i++) acc[i] = fmaf(Wsh[c][og * 4 + i], f, acc[i]);
        }
        float* hb = g_h1 + (size_t)q * NS + r;
#pragma unroll
        for (int i = 0; i < 4; i++) hb[(size_t)(og * 4 + i) * MROWS] = acc[i];

        float sv[4], qv[4];
#pragma unroll
        for (int i = 0; i < 4; i++) {
            sv[i] = acc[i];
            qv[i] = acc[i] * acc[i];
#pragma unroll
            for (int off = 1; off < 32; off <<= 1) {
                sv[i] += __shfl_xor_sync(0xffffffffu, sv[i], off);
                qv[i] += __shfl_xor_sync(0xffffffffu, qv[i], off);
            }
        }
        if (lid == 0) {
#pragma unroll
            for (int i = 0; i < 4; i++) {
                g_p1s[(size_t)(og * 4 + i) * NQ + q] = sv[i];
                g_p1q[(size_t)(og * 4 + i) * NQ + q] = qv[i];
            }
        }
    }
}

__global__ void __launch_bounds__(512, 2) fused_fps_ball(const float* __restrict__ xyz,
                                                         const float* __restrict__ points,
                                                         const float* __restrict__ W0,
                                                         const float* __restrict__ b0,
                                                         float* __restrict__ out0) {
    __shared__ u64 swk[2][16];
    __shared__ float4 swc[2][16];
    __shared__ u64 cand[CAP];
    __shared__ u32 scnt;
    __shared__ u64 gm[16];
    __shared__ u64 sgmin;
    __shared__ u64 sel[NS];
    __shared__ float frow[9][32];
    __shared__ float Wsh[9][64];
    __shared__ float bsh[64];

    const int bid = blockIdx.x;
    if (bid < NB) {
        fps_body(bid, xyz, out0, swk, swc);
    } else {
        int b, s;
        if (bid >= 148 && bid < 148 + NB) {
            s = NP - 1; b = bid - 148;
        } else {
            int idx = (bid < 148) ? (bid - NB) : (bid - 2 * NB);
            b = idx & 15; s = idx >> 4;
        }
        ball_body(b, s, xyz, points, W0, b0,
                  cand, &scnt, gm, &sgmin, sel, frow, Wsh, bsh);
    }
}

// =======================================================================
// comb_part: BN coeffs from per-channel partial arrays (stride n).
// =======================================================================
__global__ void __launch_bounds__(256) comb_part(const float* __restrict__ ps,
                                                 const float* __restrict__ pq,
                                                 const float* __restrict__ g,
                                                 const float* __restrict__ be,
                                                 float* __restrict__ a,
                                                 float* __restrict__ c, int n) {
    const int ch = blockIdx.x, tid = threadIdx.x;
    const float* s0 = ps + (size_t)ch * n;
    const float* q0 = pq + (size_t)ch * n;
    float s = 0.f, s2 = 0.f;
    for (int i = tid; i < n; i += 256) { s += s0[i]; s2 += q0[i]; }
    __shared__ float sh[256], sh2[256];
    sh[tid] = s; sh2[tid] = s2;
    __syncthreads();
    for (int off = 128; off > 0; off >>= 1) {
        if (tid < off) { sh[tid] += sh[tid + off]; sh2[tid] += sh2[tid + off]; }
        __syncthreads();
    }
    if (tid == 0) {
        double mean = (double)sh[0] / (double)MROWS;
        double var = (double)sh2[0] / (double)MROWS - mean * mean;
        double af = (double)g[ch] / sqrt(var + 1e-5);
        a[ch] = (float)af;
        c[ch] = (float)((double)be[ch] - mean * af);
    }
}

// =======================================================================
// MLP layer 2 (64->64), 512 thr, 16 accs; input tile (256 rows x 64 ch,
// BN+relu pre-applied) staged in 64KB dynamic smem -> mainloop is LDS-only.
// =======================================================================
__global__ void __launch_bounds__(512, 2) mlp2_kernel(const float* __restrict__ in,
                                                      const float* __restrict__ W,
                                                      const float* __restrict__ bias,
                                                      const float* __restrict__ aP,
                                                      const float* __restrict__ cP,
                                                      float* __restrict__ out) {
    extern __shared__ float xs[];              // [64][256] = 64KB
    __shared__ __align__(16) float Wsh[64][64];
    __shared__ float bsh[64], ash[64], csh[64];
    __shared__ u64 sS[16][8], sQ[16][8];
    const int tid = threadIdx.x, wid = tid >> 5, lid = tid & 31;
    const int rt = tid & 127, quarter = tid >> 7;
    const int o0 = quarter * 16;
    const size_t r0b = (size_t)blockIdx.x * 256;

    for (int i = tid; i < 64 * 64; i += 512) {
        int c = i >> 6, o = i & 63;
        Wsh[c][o] = W[(size_t)o * 64 + c];
    }
    if (tid < 64) { bsh[tid] = bias[tid]; ash[tid] = aP[tid]; csh[tid] = cP[tid]; }
    __syncthreads();

    // stage input tile with BN+relu (one read per element)
    for (int i = tid; i < 4096; i += 512) {
        int c = i >> 6, j = i & 63;
        float4 v = *reinterpret_cast<const float4*>(in + (size_t)c * MROWS + r0b + 4 * j);
        float av = ash[c], cv = csh[c];
        v.x = fmaxf(fmaf(av, v.x, cv), 0.0f);
        v.y = fmaxf(fmaf(av, v.y, cv), 0.0f);
        v.z = fmaxf(fmaf(av, v.z, cv), 0.0f);
        v.w = fmaxf(fmaf(av, v.w, cv), 0.0f);
        *reinterpret_cast<float4*>(&xs[c * 256 + 4 * j]) = v;
    }
    __syncthreads();

    u64 acc[16];
#pragma unroll
    for (int k = 0; k < 8; k++) {
        u64 bb = pk(bsh[o0 + 2 * k], bsh[o0 + 2 * k + 1]);
        acc[k] = bb; acc[8 + k] = bb;
    }

#pragma unroll 8
    for (int c = 0; c < 64; c++) {
        float xa = xs[c * 256 + rt];
        float xb = xs[c * 256 + rt + 128];
        u64 x0 = pk(xa, xa), x1 = pk(xb, xb);
        const ulonglong2* w4 = reinterpret_cast<const ulonglong2*>(&Wsh[c][o0]);
#pragma unroll
        for (int k4 = 0; k4 < 4; k4++) {
            ulonglong2 w = w4[k4];
            fma2(acc[2 * k4 + 0], w.x, x0);
            fma2(acc[2 * k4 + 1], w.y, x0);
            fma2(acc[8 + 2 * k4 + 0], w.x, x1);
            fma2(acc[8 + 2 * k4 + 1], w.y, x1);
        }
    }

    float* outr = out + r0b + rt;
#pragma unroll
    for (int k = 0; k < 8; k++) {
        float lo, hi;
        upk(acc[k], lo, hi);
        outr[(size_t)(o0 + 2 * k) * MROWS] = lo;
        outr[(size_t)(o0 + 2 * k + 1) * MROWS] = hi;
        upk(acc[8 + k], lo, hi);
        outr[(size_t)(o0 + 2 * k) * MROWS + 128] = lo;
        outr[(size_t)(o0 + 2 * k + 1) * MROWS + 128] = hi;
    }

    // per-block stat partials
#pragma unroll
    for (int k = 0; k < 8; k++) {
        u64 sv = addx2(acc[k], acc[8 + k]);
        u64 qv = addx2(mulx2(acc[k], acc[k]), mulx2(acc[8 + k], acc[8 + k]));
#pragma unroll
        for (int off = 1; off < 32; off <<= 1) {
            sv = addx2(sv, __shfl_xor_sync(0xffffffffu, sv, off));
            qv = addx2(qv, __shfl_xor_sync(0xffffffffu, qv, off));
        }
        if (lid == 0) { sS[wid][k] = sv; sQ[wid][k] = qv; }
    }
    __syncthreads();
    if (tid < 128) {
        int ch = tid & 63;
        bool isq = tid >= 64;
        int qc = ch >> 4, k = (ch & 15) >> 1, lohi = ch & 1;
        const u64 (*src)[8] = isq ? sQ : sS;
        u64 t = src[4 * qc][k];
#pragma unroll
        for (int w = 1; w < 4; w++) t = addx2(t, src[4 * qc + w][k]);
        float lo, hi; upk(t, lo, hi);
        (isq ? g_p2q : g_p2s)[(size_t)ch * MB2 + blockIdx.x] = lohi ? hi : lo;
    }
}

// =======================================================================
// MLP layer 3 (64->128 via y-halves), 512 thr, 16 accs, smem-staged
// input, NO h3 store. Epilogue: stat partials + per-query channel max.
// =======================================================================
__global__ void __launch_bounds__(512, 2) mlp3_kernel(const float* __restrict__ in,
                                                      const float* __restrict__ W,
                                                      const float* __restrict__ bias,
                                                      const float* __restrict__ aP,
                                                      const float* __restrict__ cP) {
    extern __shared__ float xs[];              // [64][256] = 64KB
    __shared__ __align__(16) float Wsh[64][64];
    __shared__ float bsh[64], ash[64], csh[64];
    __shared__ u64 sS[16][8], sQ[16][8];
    const int tid = threadIdx.x, wid = tid >> 5, lid = tid & 31;
    const int rt = tid & 127, quarter = tid >> 7;
    const int o0 = quarter * 16;
    const int ocb = blockIdx.y * 64;
    const size_t r0b = (size_t)blockIdx.x * 256;

    for (int i = tid; i < 64 * 64; i += 512) {
        int c = i >> 6, o = i & 63;
        Wsh[c][o] = W[(size_t)(ocb + o) * 64 + c];
    }
    if (tid < 64) { bsh[tid] = bias[ocb + tid]; ash[tid] = aP[tid]; csh[tid] = cP[tid]; }
    __syncthreads();

    for (int i = tid; i < 4096; i += 512) {
        int c = i >> 6, j = i & 63;
        float4 v = *reinterpret_cast<const float4*>(in + (size_t)c * MROWS + r0b + 4 * j);
        float av = ash[c], cv = csh[c];
        v.x = fmaxf(fmaf(av, v.x, cv), 0.0f);
        v.y = fmaxf(fmaf(av, v.y, cv), 0.0f);
        v.z = fmaxf(fmaf(av, v.z, cv), 0.0f);
        v.w = fmaxf(fmaf(av, v.w, cv), 0.0f);
        *reinterpret_cast<float4*>(&xs[c * 256 + 4 * j]) = v;
    }
    __syncthreads();

    u64 acc[16];
#pragma unroll
    for (int k = 0; k < 8; k++) {
        u64 bb = pk(bsh[o0 + 2 * k], bsh[o0 + 2 * k + 1]);
        acc[k] = bb; acc[8 + k] = bb;
    }

#pragma unroll 8
    for (int c = 0; c < 64; c++) {
        float xa = xs[c * 256 + rt];
        float xb = xs[c * 256 + rt + 128];
        u64 x0 = pk(xa, xa), x1 = pk(xb, xb);
        const ulonglong2* w4 = reinterpret_cast<const ulonglong2*>(&Wsh[c][o0]);
#pragma unroll
        for (int k4 = 0; k4 < 4; k4++) {
            ulonglong2 w = w4[k4];
            fma2(acc[2 * k4 + 0], w.x, x0);
            fma2(acc[2 * k4 + 1], w.y, x0);
            fma2(acc[8 + 2 * k4 + 0], w.x, x1);
            fma2(acc[8 + 2 * k4 + 1], w.y, x1);
        }
    }

    // stat partials
#pragma unroll
    for (int k = 0; k < 8; k++) {
        u64 sv = addx2(acc[k], acc[8 + k]);
        u64 qv = addx2(mulx2(acc[k], acc[k]), mulx2(acc[8 + k], acc[8 + k]));
#pragma unroll
        for (int off = 1; off < 32; off <<= 1) {
            sv = addx2(sv, __shfl_xor_sync(0xffffffffu, sv, off));
            qv = addx2(qv, __shfl_xor_sync(0xffffffffu, qv, off));
        }
        if (lid == 0) { sS[wid][k] = sv; sQ[wid][k] = qv; }
    }

    // hmax: warp lanes = 32 consecutive rows = one query (x2 row halves)
    {
        const int qa = blockIdx.x * 8 + (wid & 3);
        const int qb = qa + 4;
        const int cb2 = (ocb + o0) >> 1;
        float2* hmax2 = reinterpret_cast<float2*>(g_hmax);
#pragma unroll
        for (int k = 0; k < 8; k++) {
            float lo, hi;
            upk(acc[k], lo, hi);
            u32 a0 = rmaxu(f2ord(lo)), b0v = rmaxu(f2ord(hi));
            upk(acc[8 + k], lo, hi);
            u32 a1 = rmaxu(f2ord(lo)), b1v = rmaxu(f2ord(hi));
            if (lid == 0) {
                hmax2[(size_t)qa * 64 + cb2 + k] =
                    make_float2(__uint_as_float(uno(a0)), __uint_as_float(uno(b0v)));
                hmax2[(size_t)qb * 64 + cb2 + k] =
                    make_float2(__uint_as_float(uno(a1)), __uint_as_float(uno(b1v)));
            }
        }
    }
    __syncthreads();
    if (tid < 128) {
        int ch = tid & 63;
        bool isq = tid >= 64;
        int qc = ch >> 4, k = (ch & 15) >> 1, lohi = ch & 1;
        const u64 (*src)[8] = isq ? sQ : sS;
        u64 t = src[4 * qc][k];
#pragma unroll
        for (int w = 1; w < 4; w++) t = addx2(t, src[4 * qc + w][k]);
        float lo, hi; upk(t, lo, hi);
        (isq ? g_p3q : g_p3s)[(size_t)(ocb + ch) * MB2 + blockIdx.x] = lohi ? hi : lo;
    }
}

// =======================================================================
// final: out = relu(a3*hmax + c3)  (a3>0 so max commutes exactly)
// =======================================================================
__global__ void __launch_bounds__(1024) final_kernel(float* __restrict__ out) {
    const int t = blockIdx.x * 1024 + threadIdx.x;
    const int q = t >> 7, o = t & 127;
    float v = g_hmax[t];
    float y = fmaxf(fmaf(g_a3[o], v, g_c3[o]), 0.0f);
    const int b = q >> 9, s = q & 511;
    out[(size_t)NB * 3 * NP + (((size_t)b * 128 + o) << 9) + s] = y;
}

// ---------------- launch ----------------
extern "C" void kernel_launch(void* const* d_in, const int* in_sizes, int n_in,
                              void* d_out, int out_size) {
    const float* xyz = (const float*)d_in[0];
    const float* pts = (const float*)d_in[1];
    const float* W0 = (const float*)d_in[2];
    const float* b0 = (const float*)d_in[3];
    const float* g0 = (const float*)d_in[4];
    const float* be0 = (const float*)d_in[5];
    const float* W1 = (const float*)d_in[6];
    const float* b1 = (const float*)d_in[7];
    const float* g1 = (const float*)d_in[8];
    const float* be1 = (const float*)d_in[9];
    const float* W2 = (const float*)d_in[10];
    const float* b2 = (const float*)d_in[11];
    const float* g2 = (const float*)d_in[12];
    const float* be2 = (const float*)d_in[13];
    float* out = (float*)d_out;

    void *h1, *h2, *a1, *c1, *a2, *c2, *a3, *c3;
    void *p1s, *p1q, *p2s, *p2q, *p3s, *p3q;
    cudaGetSymbolAddress(&h1, g_h1);
    cudaGetSymbolAddress(&h2, g_h2);
    cudaGetSymbolAddress(&a1, g_a1);
    cudaGetSymbolAddress(&c1, g_c1);
    cudaGetSymbolAddress(&a2, g_a2);
    cudaGetSymbolAddress(&c2, g_c2);
    cudaGetSymbolAddress(&a3, g_a3);
    cudaGetSymbolAddress(&c3, g_c3);
    cudaGetSymbolAddress(&p1s, g_p1s);
    cudaGetSymbolAddress(&p1q, g_p1q);
    cudaGetSymbolAddress(&p2s, g_p2s);
    cudaGetSymbolAddress(&p2q, g_p2q);
    cudaGetSymbolAddress(&p3s, g_p3s);
    cudaGetSymbolAddress(&p3q, g_p3q);

    const int mlp_smem = 64 * 256 * 4;   // 64KB input tile
    cudaFuncSetAttribute(mlp2_kernel, cudaFuncAttributeMaxDynamicSharedMemorySize, mlp_smem);
    cudaFuncSetAttribute(mlp3_kernel, cudaFuncAttributeMaxDynamicSharedMemorySize, mlp_smem);

    init_kernel<<<1, 32>>>();
    fused_fps_ball<<<NB + NB * NP, 512>>>(xyz, pts, W0, b0, out);
    comb_part<<<64, 256>>>((const float*)p1s, (const float*)p1q, g0, be0,
                           (float*)a1, (float*)c1, NQ);

    // launch #4 -> ncu profiles mlp2_kernel
    mlp2_kernel<<<MB2, 512, mlp_smem>>>((const float*)h1, W1, b1,
                                        (const float*)a1, (const float*)c1, (float*)h2);

    comb_part<<<64, 256>>>((const float*)p2s, (const float*)p2q, g1, be1,
                           (float*)a2, (float*)c2, MB2);

    mlp3_kernel<<<dim3(MB2, 2), 512, mlp_smem>>>((const float*)h2, W2, b2,
                                                 (const float*)a2, (const float*)c2);
    comb_part<<<128, 256>>>((const float*)p3s, (const float*)p3q, g2, be2,
                            (float*)a3, (float*)c3, MB2);
    final_kernel<<<NQ * 128 / 1024, 1024>>>(out);
}